// round 7
// baseline (speedup 1.0000x reference)
#include <cuda_runtime.h>
#include <cstdint>

// SGU: out = (xh * (tril(W) @ LN(gate) + bias)) @ proj_w + proj_b
// Pure fp32 SIMT (proven-correct R1 dataflow), inner loops use packed
// fma.rn.f32x2 (sm_100+ family PTX, 2x FP32 FMA throughput on sm_103a).

constexpr int SEQ  = 4096;
constexpr int DH   = 2048;
constexpr int DOUT = 1024;
constexpr int XW   = 2 * DH;  // 4096

typedef unsigned long long u64;

// Scratch (device globals — no runtime allocation allowed)
__device__ __align__(256) float g_gate[(size_t)SEQ * DH];  // LayerNormed gate
__device__ __align__(256) float g_mix [(size_t)SEQ * DH];  // tril(W)@gate + bias

// ---------------------------------------------------------------------------
// f32x2 packed helpers
// ---------------------------------------------------------------------------
__device__ __forceinline__ void fma2(u64& acc, u64 a, u64 b) {
    asm("fma.rn.f32x2 %0, %1, %2, %0;" : "+l"(acc) : "l"(a), "l"(b));
}
__device__ __forceinline__ float2 unpack2(u64 v) {
    float2 r;
    asm("mov.b64 {%0, %1}, %2;" : "=f"(r.x), "=f"(r.y) : "l"(v));
    return r;
}

// ---------------------------------------------------------------------------
// Kernel 1: LayerNorm (scale only, eps=1e-5) over the gate half of x.
// ---------------------------------------------------------------------------
__global__ void __launch_bounds__(256) ln_kernel(const float* __restrict__ x,
                                                 const float* __restrict__ ln_scale) {
    int row = blockIdx.x;
    const float* g = x + (size_t)row * XW + DH;
    float* out = g_gate + (size_t)row * DH;
    int t = threadIdx.x;

    float vals[8];
    float sum = 0.f, sq = 0.f;
#pragma unroll
    for (int i = 0; i < 8; i++) {
        float v = g[t + i * 256];
        vals[i] = v;
        sum += v;
        sq  += v * v;
    }
#pragma unroll
    for (int o = 16; o; o >>= 1) {
        sum += __shfl_xor_sync(0xffffffffu, sum, o);
        sq  += __shfl_xor_sync(0xffffffffu, sq,  o);
    }
    __shared__ float ssum[8], ssq[8];
    __shared__ float s_mean, s_rstd;
    if ((t & 31) == 0) { ssum[t >> 5] = sum; ssq[t >> 5] = sq; }
    __syncthreads();
    if (t == 0) {
        float S = 0.f, Q = 0.f;
#pragma unroll
        for (int i = 0; i < 8; i++) { S += ssum[i]; Q += ssq[i]; }
        float mean = S * (1.f / DH);
        float var  = Q * (1.f / DH) - mean * mean;
        s_mean = mean;
        s_rstd = rsqrtf(var + 1e-5f);
    }
    __syncthreads();
    float mean = s_mean, rstd = s_rstd;
#pragma unroll
    for (int i = 0; i < 8; i++) {
        int c = t + i * 256;
        out[c] = (vals[i] - mean) * rstd * ln_scale[c];
    }
}

// ---------------------------------------------------------------------------
// Kernel 2: g_mix = tril(W) @ g_gate + bias
// 128x128 tile, BK=8, 256 threads, 8x8 regs/thread, f32x2 packed FMA.
// A stored DUPLICATED in smem so LDS.128 yields {a,a,a',a'} packed pairs.
// ---------------------------------------------------------------------------
__global__ void __launch_bounds__(256) mix_kernel(const float* __restrict__ W,
                                                  const float* __restrict__ bias) {
    constexpr int BK = 8;
    __shared__ __align__(16) float As[BK][256];  // duplicated: [k][2m],[2m+1]
    __shared__ __align__(16) float Bs[BK][128];

    int bx = blockIdx.x, by = blockIdx.y;
    int tid = threadIdx.x;
    int row0 = by * 128;
    int col0 = bx * 128;
    int kEnd = row0 + 128;  // causal truncation

    int tx = tid & 15;      // N direction (8 cols)
    int ty = tid >> 4;      // M direction (8 rows)

    int a_row = tid >> 1;          // 0..127
    int a_col = (tid & 1) * 4;     // 0 or 4
    int b_row = tid >> 5;          // 0..7
    int b_col = (tid & 31) * 4;    // 0..124

    u64 acc[8][4];
#pragma unroll
    for (int i = 0; i < 8; i++)
#pragma unroll
        for (int j = 0; j < 4; j++) acc[i][j] = 0ull;

    int m = row0 + a_row;

    // prefetch stage 0
    float4 av = *reinterpret_cast<const float4*>(W + (size_t)m * SEQ + a_col);
    {
        int kg = a_col;
        if (kg + 0 > m) av.x = 0.f;
        if (kg + 1 > m) av.y = 0.f;
        if (kg + 2 > m) av.z = 0.f;
        if (kg + 3 > m) av.w = 0.f;
    }
    float4 bv = *reinterpret_cast<const float4*>(g_gate + (size_t)b_row * DH + col0 + b_col);

    for (int k0 = 0; k0 < kEnd; k0 += BK) {
        // store current stage (duplicated A)
        As[a_col + 0][2 * a_row] = av.x;  As[a_col + 0][2 * a_row + 1] = av.x;
        As[a_col + 1][2 * a_row] = av.y;  As[a_col + 1][2 * a_row + 1] = av.y;
        As[a_col + 2][2 * a_row] = av.z;  As[a_col + 2][2 * a_row + 1] = av.z;
        As[a_col + 3][2 * a_row] = av.w;  As[a_col + 3][2 * a_row + 1] = av.w;
        *reinterpret_cast<float4*>(&Bs[b_row][b_col]) = bv;
        __syncthreads();

        // prefetch next stage into registers
        if (k0 + BK < kEnd) {
            int kg = k0 + BK + a_col;
            av = *reinterpret_cast<const float4*>(W + (size_t)m * SEQ + kg);
            if (kg + 0 > m) av.x = 0.f;
            if (kg + 1 > m) av.y = 0.f;
            if (kg + 2 > m) av.z = 0.f;
            if (kg + 3 > m) av.w = 0.f;
            bv = *reinterpret_cast<const float4*>(
                g_gate + (size_t)(k0 + BK + b_row) * DH + col0 + b_col);
        }

#pragma unroll
        for (int k = 0; k < BK; k++) {
            ulonglong2 a01 = *reinterpret_cast<const ulonglong2*>(&As[k][ty * 16 + 0]);
            ulonglong2 a23 = *reinterpret_cast<const ulonglong2*>(&As[k][ty * 16 + 4]);
            ulonglong2 a45 = *reinterpret_cast<const ulonglong2*>(&As[k][ty * 16 + 8]);
            ulonglong2 a67 = *reinterpret_cast<const ulonglong2*>(&As[k][ty * 16 + 12]);
            ulonglong2 b03 = *reinterpret_cast<const ulonglong2*>(&Bs[k][tx * 8 + 0]);
            ulonglong2 b47 = *reinterpret_cast<const ulonglong2*>(&Bs[k][tx * 8 + 4]);
            u64 ad[8] = { a01.x, a01.y, a23.x, a23.y, a45.x, a45.y, a67.x, a67.y };
            u64 bd[4] = { b03.x, b03.y, b47.x, b47.y };
#pragma unroll
            for (int i = 0; i < 8; i++)
#pragma unroll
                for (int j = 0; j < 4; j++) fma2(acc[i][j], ad[i], bd[j]);
        }
        __syncthreads();
    }

#pragma unroll
    for (int i = 0; i < 8; i++) {
        int row = row0 + ty * 8 + i;
        float b = bias[row];
        float* dst = g_mix + (size_t)row * DH + col0 + tx * 8;
#pragma unroll
        for (int j = 0; j < 4; j++) {
            float2 v = unpack2(acc[i][j]);
            float2 o = { v.x + b, v.y + b };
            *reinterpret_cast<float2*>(dst + 2 * j) = o;
        }
    }
}

// ---------------------------------------------------------------------------
// Kernel 3: out = (xh * g_mix) @ proj_w + proj_b
// Same structure; A[m,k] = x[m,k]*g_mix[m,k] fused into the A-tile load.
// ---------------------------------------------------------------------------
__global__ void __launch_bounds__(256) proj_kernel(const float* __restrict__ x,
                                                   const float* __restrict__ P,
                                                   const float* __restrict__ pb,
                                                   float* __restrict__ out) {
    constexpr int BK = 8;
    __shared__ __align__(16) float As[BK][256];
    __shared__ __align__(16) float Bs[BK][128];

    int bx = blockIdx.x, by = blockIdx.y;
    int tid = threadIdx.x;
    int row0 = by * 128;
    int col0 = bx * 128;

    int tx = tid & 15;
    int ty = tid >> 4;

    int a_row = tid >> 1;
    int a_col = (tid & 1) * 4;
    int b_row = tid >> 5;
    int b_col = (tid & 31) * 4;

    u64 acc[8][4];
#pragma unroll
    for (int i = 0; i < 8; i++)
#pragma unroll
        for (int j = 0; j < 4; j++) acc[i][j] = 0ull;

    int m = row0 + a_row;

    float4 xv = *reinterpret_cast<const float4*>(x + (size_t)m * XW + a_col);
    float4 gv = *reinterpret_cast<const float4*>(g_mix + (size_t)m * DH + a_col);
    float4 bv = *reinterpret_cast<const float4*>(P + (size_t)b_row * DOUT + col0 + b_col);

    for (int k0 = 0; k0 < DH; k0 += BK) {
        float a0 = xv.x * gv.x, a1 = xv.y * gv.y, a2 = xv.z * gv.z, a3 = xv.w * gv.w;
        As[a_col + 0][2 * a_row] = a0;  As[a_col + 0][2 * a_row + 1] = a0;
        As[a_col + 1][2 * a_row] = a1;  As[a_col + 1][2 * a_row + 1] = a1;
        As[a_col + 2][2 * a_row] = a2;  As[a_col + 2][2 * a_row + 1] = a2;
        As[a_col + 3][2 * a_row] = a3;  As[a_col + 3][2 * a_row + 1] = a3;
        *reinterpret_cast<float4*>(&Bs[b_row][b_col]) = bv;
        __syncthreads();

        if (k0 + BK < DH) {
            int kg = k0 + BK + a_col;
            xv = *reinterpret_cast<const float4*>(x + (size_t)m * XW + kg);
            gv = *reinterpret_cast<const float4*>(g_mix + (size_t)m * DH + kg);
            bv = *reinterpret_cast<const float4*>(
                P + (size_t)(k0 + BK + b_row) * DOUT + col0 + b_col);
        }

#pragma unroll
        for (int k = 0; k < BK; k++) {
            ulonglong2 a01 = *reinterpret_cast<const ulonglong2*>(&As[k][ty * 16 + 0]);
            ulonglong2 a23 = *reinterpret_cast<const ulonglong2*>(&As[k][ty * 16 + 4]);
            ulonglong2 a45 = *reinterpret_cast<const ulonglong2*>(&As[k][ty * 16 + 8]);
            ulonglong2 a67 = *reinterpret_cast<const ulonglong2*>(&As[k][ty * 16 + 12]);
            ulonglong2 b03 = *reinterpret_cast<const ulonglong2*>(&Bs[k][tx * 8 + 0]);
            ulonglong2 b47 = *reinterpret_cast<const ulonglong2*>(&Bs[k][tx * 8 + 4]);
            u64 ad[8] = { a01.x, a01.y, a23.x, a23.y, a45.x, a45.y, a67.x, a67.y };
            u64 bd[4] = { b03.x, b03.y, b47.x, b47.y };
#pragma unroll
            for (int i = 0; i < 8; i++)
#pragma unroll
                for (int j = 0; j < 4; j++) fma2(acc[i][j], ad[i], bd[j]);
        }
        __syncthreads();
    }

#pragma unroll
    for (int i = 0; i < 8; i++) {
        int row = row0 + ty * 8 + i;
        float* dst = out + (size_t)row * DOUT + col0 + tx * 8;
#pragma unroll
        for (int j = 0; j < 4; j++) {
            float2 v = unpack2(acc[i][j]);
            float2 pbv = *reinterpret_cast<const float2*>(pb + col0 + tx * 8 + 2 * j);
            float2 o = { v.x + pbv.x, v.y + pbv.y };
            *reinterpret_cast<float2*>(dst + 2 * j) = o;
        }
    }
}

// ---------------------------------------------------------------------------
// Launch. Inputs: x, ln_scale, spatial_weights, spatial_biases, proj_w, proj_b
// ---------------------------------------------------------------------------
extern "C" void kernel_launch(void* const* d_in, const int* in_sizes, int n_in,
                              void* d_out, int out_size) {
    const float* x    = (const float*)d_in[0];
    const float* lns  = (const float*)d_in[1];
    const float* W    = (const float*)d_in[2];
    const float* sb   = (const float*)d_in[3];
    const float* pw   = (const float*)d_in[4];
    const float* pb   = (const float*)d_in[5];
    float* out = (float*)d_out;

    ln_kernel<<<SEQ, 256>>>(x, lns);

    dim3 gmix(DH / 128, SEQ / 128);   // (16, 32)
    mix_kernel<<<gmix, 256>>>(W, sb);

    dim3 gproj(DOUT / 128, SEQ / 128); // (8, 32)
    proj_kernel<<<gproj, 256>>>(x, pw, pb, out);
}

// round 8
// speedup vs baseline: 1.5296x; 1.5296x over previous
#include <cuda_runtime.h>
#include <cstdint>

// SGU: out = (xh * (tril(W) @ LN(gate) + bias)) @ proj_w + proj_b
// fp32 SIMT with packed fma.rn.f32x2 (FFMA2), m-pair accumulators:
// a-pairs arrive pre-packed from LDS.128; only b is duplicated via mov.b64.

constexpr int SEQ  = 4096;
constexpr int DH   = 2048;
constexpr int DOUT = 1024;
constexpr int XW   = 2 * DH;  // 4096

typedef unsigned long long u64;

// Scratch (device globals — no runtime allocation allowed)
__device__ __align__(256) float g_gate[(size_t)SEQ * DH];  // LayerNormed gate
__device__ __align__(256) float g_mix [(size_t)SEQ * DH];  // tril(W)@gate + bias

// ---------------------------------------------------------------------------
// f32x2 packed helpers
// ---------------------------------------------------------------------------
__device__ __forceinline__ void fma2(u64& acc, u64 a, u64 b) {
    asm("fma.rn.f32x2 %0, %1, %2, %0;" : "+l"(acc) : "l"(a), "l"(b));
}
__device__ __forceinline__ u64 dup2(float v) {
    u64 r;
    uint32_t u = __float_as_uint(v);
    asm("mov.b64 %0, {%1, %2};" : "=l"(r) : "r"(u), "r"(u));
    return r;
}
__device__ __forceinline__ float2 unpack2(u64 v) {
    float2 r;
    asm("mov.b64 {%0, %1}, %2;" : "=f"(r.x), "=f"(r.y) : "l"(v));
    return r;
}

// ---------------------------------------------------------------------------
// Kernel 1: LayerNorm (scale only, eps=1e-5) over the gate half of x.
// ---------------------------------------------------------------------------
__global__ void __launch_bounds__(256) ln_kernel(const float* __restrict__ x,
                                                 const float* __restrict__ ln_scale) {
    int row = blockIdx.x;
    const float* g = x + (size_t)row * XW + DH;
    float* out = g_gate + (size_t)row * DH;
    int t = threadIdx.x;

    float vals[8];
    float sum = 0.f, sq = 0.f;
#pragma unroll
    for (int i = 0; i < 8; i++) {
        float v = g[t + i * 256];
        vals[i] = v;
        sum += v;
        sq  += v * v;
    }
#pragma unroll
    for (int o = 16; o; o >>= 1) {
        sum += __shfl_xor_sync(0xffffffffu, sum, o);
        sq  += __shfl_xor_sync(0xffffffffu, sq,  o);
    }
    __shared__ float ssum[8], ssq[8];
    __shared__ float s_mean, s_rstd;
    if ((t & 31) == 0) { ssum[t >> 5] = sum; ssq[t >> 5] = sq; }
    __syncthreads();
    if (t == 0) {
        float S = 0.f, Q = 0.f;
#pragma unroll
        for (int i = 0; i < 8; i++) { S += ssum[i]; Q += ssq[i]; }
        float mean = S * (1.f / DH);
        float var  = Q * (1.f / DH) - mean * mean;
        s_mean = mean;
        s_rstd = rsqrtf(var + 1e-5f);
    }
    __syncthreads();
    float mean = s_mean, rstd = s_rstd;
#pragma unroll
    for (int i = 0; i < 8; i++) {
        int c = t + i * 256;
        out[c] = (vals[i] - mean) * rstd * ln_scale[c];
    }
}

// ---------------------------------------------------------------------------
// Shared GEMM inner-loop shape:
// 128x128 tile, BK=8, 256 threads. Thread (tx,ty): rows ty*8..+7 (4 m-pairs),
// cols {tx*4..+3, 64+tx*4..+3}. acc[i][j] = {C[m2i][nj], C[m2i+1][nj]}.
// ---------------------------------------------------------------------------

// ---------------------------------------------------------------------------
// Kernel 2: g_mix = tril(W) @ g_gate + bias    (causal K truncation)
// ---------------------------------------------------------------------------
__global__ void __launch_bounds__(256) mix_kernel(const float* __restrict__ W,
                                                  const float* __restrict__ bias) {
    constexpr int BK = 8;
    __shared__ __align__(16) float As[BK][128];  // transposed: As[k][m]
    __shared__ __align__(16) float Bs[BK][128];

    int bx = blockIdx.x, by = blockIdx.y;
    int tid = threadIdx.x;
    int row0 = by * 128;
    int col0 = bx * 128;
    int kEnd = row0 + 128;

    int tx = tid & 15;      // n direction
    int ty = tid >> 4;      // m direction

    int a_row = tid >> 1;          // 0..127
    int a_col = (tid & 1) * 4;     // 0 or 4
    int b_row = tid >> 5;          // 0..7
    int b_col = (tid & 31) * 4;    // 0..124

    u64 acc[4][8];
#pragma unroll
    for (int i = 0; i < 4; i++)
#pragma unroll
        for (int j = 0; j < 8; j++) acc[i][j] = 0ull;

    int m = row0 + a_row;

    float4 av = *reinterpret_cast<const float4*>(W + (size_t)m * SEQ + a_col);
    if (a_col + 0 > m) av.x = 0.f;
    if (a_col + 1 > m) av.y = 0.f;
    if (a_col + 2 > m) av.z = 0.f;
    if (a_col + 3 > m) av.w = 0.f;
    float4 bv = *reinterpret_cast<const float4*>(g_gate + (size_t)b_row * DH + col0 + b_col);

    for (int k0 = 0; k0 < kEnd; k0 += BK) {
        As[a_col + 0][a_row] = av.x;
        As[a_col + 1][a_row] = av.y;
        As[a_col + 2][a_row] = av.z;
        As[a_col + 3][a_row] = av.w;
        *reinterpret_cast<float4*>(&Bs[b_row][b_col]) = bv;
        __syncthreads();

        if (k0 + BK < kEnd) {
            int kg = k0 + BK + a_col;
            av = *reinterpret_cast<const float4*>(W + (size_t)m * SEQ + kg);
            if (kg + 0 > m) av.x = 0.f;
            if (kg + 1 > m) av.y = 0.f;
            if (kg + 2 > m) av.z = 0.f;
            if (kg + 3 > m) av.w = 0.f;
            bv = *reinterpret_cast<const float4*>(
                g_gate + (size_t)(k0 + BK + b_row) * DH + col0 + b_col);
        }

#pragma unroll
        for (int k = 0; k < BK; k++) {
            ulonglong2 a01 = *reinterpret_cast<const ulonglong2*>(&As[k][ty * 8 + 0]);
            ulonglong2 a23 = *reinterpret_cast<const ulonglong2*>(&As[k][ty * 8 + 4]);
            u64 ap[4] = { a01.x, a01.y, a23.x, a23.y };
            float4 bq0 = *reinterpret_cast<const float4*>(&Bs[k][tx * 4]);
            float4 bq1 = *reinterpret_cast<const float4*>(&Bs[k][64 + tx * 4]);
            u64 bb[8] = { dup2(bq0.x), dup2(bq0.y), dup2(bq0.z), dup2(bq0.w),
                          dup2(bq1.x), dup2(bq1.y), dup2(bq1.z), dup2(bq1.w) };
#pragma unroll
            for (int i = 0; i < 4; i++)
#pragma unroll
                for (int j = 0; j < 8; j++) fma2(acc[i][j], ap[i], bb[j]);
        }
        __syncthreads();
    }

    // epilogue: +bias; rows ty*8+2i (lo) and +1 (hi); cols tx*4 and 64+tx*4
#pragma unroll
    for (int i = 0; i < 4; i++) {
        int r_lo = row0 + ty * 8 + 2 * i;
        float b_lo = bias[r_lo];
        float b_hi = bias[r_lo + 1];
        float2 v0 = unpack2(acc[i][0]), v1 = unpack2(acc[i][1]);
        float2 v2 = unpack2(acc[i][2]), v3 = unpack2(acc[i][3]);
        float2 v4 = unpack2(acc[i][4]), v5 = unpack2(acc[i][5]);
        float2 v6 = unpack2(acc[i][6]), v7 = unpack2(acc[i][7]);
        float4 lo0 = { v0.x + b_lo, v1.x + b_lo, v2.x + b_lo, v3.x + b_lo };
        float4 lo1 = { v4.x + b_lo, v5.x + b_lo, v6.x + b_lo, v7.x + b_lo };
        float4 hi0 = { v0.y + b_hi, v1.y + b_hi, v2.y + b_hi, v3.y + b_hi };
        float4 hi1 = { v4.y + b_hi, v5.y + b_hi, v6.y + b_hi, v7.y + b_hi };
        float* d0 = g_mix + (size_t)r_lo * DH + col0;
        float* d1 = g_mix + (size_t)(r_lo + 1) * DH + col0;
        *reinterpret_cast<float4*>(d0 + tx * 4)      = lo0;
        *reinterpret_cast<float4*>(d0 + 64 + tx * 4) = lo1;
        *reinterpret_cast<float4*>(d1 + tx * 4)      = hi0;
        *reinterpret_cast<float4*>(d1 + 64 + tx * 4) = hi1;
    }
}

// ---------------------------------------------------------------------------
// Kernel 3: out = (xh * g_mix) @ proj_w + proj_b
// ---------------------------------------------------------------------------
__global__ void __launch_bounds__(256) proj_kernel(const float* __restrict__ x,
                                                   const float* __restrict__ P,
                                                   const float* __restrict__ pb,
                                                   float* __restrict__ out) {
    constexpr int BK = 8;
    __shared__ __align__(16) float As[BK][128];
    __shared__ __align__(16) float Bs[BK][128];

    int bx = blockIdx.x, by = blockIdx.y;
    int tid = threadIdx.x;
    int row0 = by * 128;
    int col0 = bx * 128;

    int tx = tid & 15;
    int ty = tid >> 4;

    int a_row = tid >> 1;
    int a_col = (tid & 1) * 4;
    int b_row = tid >> 5;
    int b_col = (tid & 31) * 4;

    u64 acc[4][8];
#pragma unroll
    for (int i = 0; i < 4; i++)
#pragma unroll
        for (int j = 0; j < 8; j++) acc[i][j] = 0ull;

    int m = row0 + a_row;

    float4 xv = *reinterpret_cast<const float4*>(x + (size_t)m * XW + a_col);
    float4 gv = *reinterpret_cast<const float4*>(g_mix + (size_t)m * DH + a_col);
    float4 bv = *reinterpret_cast<const float4*>(P + (size_t)b_row * DOUT + col0 + b_col);

    for (int k0 = 0; k0 < DH; k0 += BK) {
        As[a_col + 0][a_row] = xv.x * gv.x;
        As[a_col + 1][a_row] = xv.y * gv.y;
        As[a_col + 2][a_row] = xv.z * gv.z;
        As[a_col + 3][a_row] = xv.w * gv.w;
        *reinterpret_cast<float4*>(&Bs[b_row][b_col]) = bv;
        __syncthreads();

        if (k0 + BK < DH) {
            int kg = k0 + BK + a_col;
            xv = *reinterpret_cast<const float4*>(x + (size_t)m * XW + kg);
            gv = *reinterpret_cast<const float4*>(g_mix + (size_t)m * DH + kg);
            bv = *reinterpret_cast<const float4*>(
                P + (size_t)(k0 + BK + b_row) * DOUT + col0 + b_col);
        }

#pragma unroll
        for (int k = 0; k < BK; k++) {
            ulonglong2 a01 = *reinterpret_cast<const ulonglong2*>(&As[k][ty * 8 + 0]);
            ulonglong2 a23 = *reinterpret_cast<const ulonglong2*>(&As[k][ty * 8 + 4]);
            u64 ap[4] = { a01.x, a01.y, a23.x, a23.y };
            float4 bq0 = *reinterpret_cast<const float4*>(&Bs[k][tx * 4]);
            float4 bq1 = *reinterpret_cast<const float4*>(&Bs[k][64 + tx * 4]);
            u64 bb[8] = { dup2(bq0.x), dup2(bq0.y), dup2(bq0.z), dup2(bq0.w),
                          dup2(bq1.x), dup2(bq1.y), dup2(bq1.z), dup2(bq1.w) };
#pragma unroll
            for (int i = 0; i < 4; i++)
#pragma unroll
                for (int j = 0; j < 8; j++) fma2(acc[i][j], ap[i], bb[j]);
        }
        __syncthreads();
    }

#pragma unroll
    for (int i = 0; i < 4; i++) {
        int r_lo = row0 + ty * 8 + 2 * i;
        float4 p0 = *reinterpret_cast<const float4*>(pb + col0 + tx * 4);
        float4 p1 = *reinterpret_cast<const float4*>(pb + col0 + 64 + tx * 4);
        float2 v0 = unpack2(acc[i][0]), v1 = unpack2(acc[i][1]);
        float2 v2 = unpack2(acc[i][2]), v3 = unpack2(acc[i][3]);
        float2 v4 = unpack2(acc[i][4]), v5 = unpack2(acc[i][5]);
        float2 v6 = unpack2(acc[i][6]), v7 = unpack2(acc[i][7]);
        float4 lo0 = { v0.x + p0.x, v1.x + p0.y, v2.x + p0.z, v3.x + p0.w };
        float4 lo1 = { v4.x + p1.x, v5.x + p1.y, v6.x + p1.z, v7.x + p1.w };
        float4 hi0 = { v0.y + p0.x, v1.y + p0.y, v2.y + p0.z, v3.y + p0.w };
        float4 hi1 = { v4.y + p1.x, v5.y + p1.y, v6.y + p1.z, v7.y + p1.w };
        float* d0 = out + (size_t)r_lo * DOUT + col0;
        float* d1 = out + (size_t)(r_lo + 1) * DOUT + col0;
        *reinterpret_cast<float4*>(d0 + tx * 4)      = lo0;
        *reinterpret_cast<float4*>(d0 + 64 + tx * 4) = lo1;
        *reinterpret_cast<float4*>(d1 + tx * 4)      = hi0;
        *reinterpret_cast<float4*>(d1 + 64 + tx * 4) = hi1;
    }
}

// ---------------------------------------------------------------------------
// Launch. Inputs: x, ln_scale, spatial_weights, spatial_biases, proj_w, proj_b
// ---------------------------------------------------------------------------
extern "C" void kernel_launch(void* const* d_in, const int* in_sizes, int n_in,
                              void* d_out, int out_size) {
    const float* x    = (const float*)d_in[0];
    const float* lns  = (const float*)d_in[1];
    const float* W    = (const float*)d_in[2];
    const float* sb   = (const float*)d_in[3];
    const float* pw   = (const float*)d_in[4];
    const float* pb   = (const float*)d_in[5];
    float* out = (float*)d_out;

    ln_kernel<<<SEQ, 256>>>(x, lns);

    dim3 gmix(DH / 128, SEQ / 128);   // (16, 32)
    mix_kernel<<<gmix, 256>>>(W, sb);

    dim3 gproj(DOUT / 128, SEQ / 128); // (8, 32)
    proj_kernel<<<gproj, 256>>>(x, pw, pb, out);
}